// round 4
// baseline (speedup 1.0000x reference)
#include <cuda_runtime.h>
#include <cstdint>

#define BATCH 64
#define TLEN  512
#define IDIM  1024
#define HDIM  1024
#define NG    4096
#define NCTA  128

// ---- static device scratch ----
__device__ float g_Wx[(size_t)IDIM * NG];            // packed [k][unit*4+gate], tf32-rounded
__device__ float g_Wh[(size_t)HDIM * NG];
__device__ float g_bsum[NG];
__device__ float g_xg[(size_t)TLEN * NG * BATCH];    // [t][cta][b][32]
__device__ float g_h[2][BATCH * HDIM];
__device__ unsigned g_cnt, g_gen;

__device__ __forceinline__ uint32_t rna_u(float x) {
    uint32_t u; asm("cvt.rna.tf32.f32 %0, %1;" : "=r"(u) : "f"(x)); return u;
}
__device__ __forceinline__ float rna_f(float x) { return __uint_as_float(rna_u(x)); }

__device__ __forceinline__ void mma8(float d[4], uint32_t a0, uint32_t a1, uint32_t a2, uint32_t a3,
                                     uint32_t b0, uint32_t b1) {
    asm volatile("mma.sync.aligned.m16n8k8.row.col.f32.tf32.tf32.f32 "
                 "{%0,%1,%2,%3},{%4,%5,%6,%7},{%8,%9},{%0,%1,%2,%3};"
                 : "+f"(d[0]), "+f"(d[1]), "+f"(d[2]), "+f"(d[3])
                 : "r"(a0), "r"(a1), "r"(a2), "r"(a3), "r"(b0), "r"(b1));
}
__device__ __forceinline__ void cp16(void* s, const void* g) {
    uint32_t a = (uint32_t)__cvta_generic_to_shared(s);
    asm volatile("cp.async.cg.shared.global [%0], [%1], 16;" ::"r"(a), "l"(g));
}
#define CP_COMMIT() asm volatile("cp.async.commit_group;")
#define CP_WAIT(N)  asm volatile("cp.async.wait_group %0;" ::"n"(N))

__device__ __forceinline__ float sigm(float x) { return 1.f / (1.f + expf(-x)); }

__device__ __forceinline__ void gridbar() {
    __syncthreads();
    if (threadIdx.x == 0) {
        unsigned g = *(volatile unsigned*)&g_gen;
        __threadfence();
        if (atomicAdd(&g_cnt, 1) == NCTA - 1) {
            g_cnt = 0; __threadfence(); atomicAdd(&g_gen, 1);
        } else {
            while (*(volatile unsigned*)&g_gen == g) {}
            __threadfence();
        }
    }
    __syncthreads();
}

// ---- prep: permute + round weights, fuse biases ----
__global__ void prep_kernel(const float* Wii, const float* Whi, const float* Wif, const float* Whf,
                            const float* Wig, const float* Whg, const float* Wio, const float* Who,
                            const float* bii, const float* bhi, const float* bif, const float* bhf,
                            const float* big, const float* bhg, const float* bio, const float* bho) {
    int idx = blockIdx.x * blockDim.x + threadIdx.x;
    if (idx >= IDIM * HDIM) return;
    int k = idx >> 10, j = idx & 1023;
    size_t base = (size_t)k * NG + j * 4;
    g_Wx[base + 0] = rna_f(Wif[idx]);
    g_Wx[base + 1] = rna_f(Wii[idx]);
    g_Wx[base + 2] = rna_f(Wig[idx]);
    g_Wx[base + 3] = rna_f(Wio[idx]);
    g_Wh[base + 0] = rna_f(Whf[idx]);
    g_Wh[base + 1] = rna_f(Whi[idx]);
    g_Wh[base + 2] = rna_f(Whg[idx]);
    g_Wh[base + 3] = rna_f(Who[idx]);
    if (idx < HDIM) {
        g_bsum[idx * 4 + 0] = bif[idx] + bhf[idx];
        g_bsum[idx * 4 + 1] = bii[idx] + bhi[idx];
        g_bsum[idx * 4 + 2] = big[idx] + bhg[idx];
        g_bsum[idx * 4 + 3] = bio[idx] + bho[idx];
    }
}

// ---- phase 1 GEMM: 128x128x16 tf32 tiles ----
#define SA1 20
#define SB1 136

__global__ void __launch_bounds__(256, 2) gemm1_kernel(const float* __restrict__ x) {
    __shared__ float As[2][128 * SA1];
    __shared__ float Bs[2][16 * SB1];
    const int tid = threadIdx.x;
    const int mt = blockIdx.x >> 5, nt = blockIdx.x & 31;
    const int wid = tid >> 5, lane = tid & 31;
    const int wm = wid & 1, wn = wid >> 1;

    const float* Abase = x + (size_t)mt * 128 * IDIM;
    const float* Bbase = g_Wx + nt * 128;

    float acc[4][4][4];
#pragma unroll
    for (int a = 0; a < 4; a++)
#pragma unroll
        for (int b = 0; b < 4; b++)
#pragma unroll
            for (int c = 0; c < 4; c++) acc[a][b][c] = 0.f;

    auto loadAB = [&](int kt, int buf) {
#pragma unroll
        for (int e = 0; e < 2; e++) {
            int id = tid * 2 + e, r = id >> 2, f4 = id & 3;
            cp16(&As[buf][r * SA1 + f4 * 4], Abase + (size_t)r * IDIM + kt * 16 + f4 * 4);
        }
#pragma unroll
        for (int e = 0; e < 2; e++) {
            int id = tid * 2 + e, r = id >> 5, f4 = id & 31;
            cp16(&Bs[buf][r * SB1 + f4 * 4], Bbase + (size_t)(kt * 16 + r) * NG + f4 * 4);
        }
        CP_COMMIT();
    };

    loadAB(0, 0);
    for (int kt = 0; kt < 64; kt++) {
        int cur = kt & 1;
        if (kt + 1 < 64) { loadAB(kt + 1, cur ^ 1); CP_WAIT(1); }
        else CP_WAIT(0);
        __syncthreads();
#pragma unroll
        for (int ks = 0; ks < 16; ks += 8) {
            uint32_t af[4][4], bf[4][2];
            int r0 = wm * 64 + (lane >> 2);
            int cc = ks + (lane & 3);
#pragma unroll
            for (int mi = 0; mi < 4; mi++) {
                int r = r0 + mi * 16;
                af[mi][0] = rna_u(As[cur][r * SA1 + cc]);
                af[mi][1] = rna_u(As[cur][(r + 8) * SA1 + cc]);
                af[mi][2] = rna_u(As[cur][r * SA1 + cc + 4]);
                af[mi][3] = rna_u(As[cur][(r + 8) * SA1 + cc + 4]);
            }
#pragma unroll
            for (int ni = 0; ni < 4; ni++) {
                int n = wn * 32 + ni * 8 + (lane >> 2);
                bf[ni][0] = __float_as_uint(Bs[cur][cc * SB1 + n]);
                bf[ni][1] = __float_as_uint(Bs[cur][(cc + 4) * SB1 + n]);
            }
#pragma unroll
            for (int mi = 0; mi < 4; mi++)
#pragma unroll
                for (int ni = 0; ni < 4; ni++)
                    mma8(acc[mi][ni], af[mi][0], af[mi][1], af[mi][2], af[mi][3],
                         bf[ni][0], bf[ni][1]);
        }
        __syncthreads();
    }
    // epilogue: +bias, scatter to [t][cta][b][32]
#pragma unroll
    for (int ni = 0; ni < 4; ni++) {
        int c = nt * 128 + wn * 32 + ni * 8 + (lane & 3) * 2;
        float bs0 = g_bsum[c], bs1 = g_bsum[c + 1];
        int blk = c >> 5, cc0 = c & 31;
#pragma unroll
        for (int mi = 0; mi < 4; mi++) {
            int r = mt * 128 + wm * 64 + mi * 16 + (lane >> 2);
#pragma unroll
            for (int h2 = 0; h2 < 2; h2++) {
                int rr = r + h2 * 8;
                int b = rr >> 9, t = rr & 511;
                size_t off = ((size_t)t * NCTA + blk) * (BATCH * 32) + (size_t)b * 32 + cc0;
                g_xg[off]     = acc[mi][ni][h2 * 2 + 0] + bs0;
                g_xg[off + 1] = acc[mi][ni][h2 * 2 + 1] + bs1;
            }
        }
    }
}

// ---- phase 2: persistent recurrence ----
#define SWH 40
#define SHA 68
#define WHS_F (1024 * SWH)
#define HA_F  (64 * SHA)
#define HA_OFF WHS_F
#define GB_OFF (WHS_F + 3 * HA_F)
#define REC_SMEM ((GB_OFF + 64 * 32) * 4)

__global__ void __launch_bounds__(256, 1) recur_kernel(float* __restrict__ out, int write_c) {
    extern __shared__ float sm[];
    float* Whs  = sm;
    float* gbuf = sm + GB_OFF;
    const int tid = threadIdx.x, cta = blockIdx.x;
    const int wid = tid >> 5, lane = tid & 31;
    const int wm = wid & 3, wn = wid >> 2;

    for (int i = tid; i < 1024 * 8; i += 256) {
        int k = i >> 3, f4 = i & 7;
        float4 v = *(const float4*)(g_Wh + (size_t)k * NG + cta * 32 + f4 * 4);
        *(float4*)(Whs + k * SWH + f4 * 4) = v;
    }
#pragma unroll
    for (int e = 0; e < 2; e++) {
        int idx = tid + e * 256;
        g_h[0][(idx >> 3) * HDIM + cta * 8 + (idx & 7)] = 0.f;
    }
    float creg[2] = {0.f, 0.f};
    __syncthreads();
    gridbar();

    for (int t = 0; t < TLEN; t++) {
        const float* h = g_h[t & 1];
        float* hn = g_h[(t + 1) & 1];
        float acc[2][4];
#pragma unroll
        for (int ni = 0; ni < 2; ni++)
#pragma unroll
            for (int c = 0; c < 4; c++) acc[ni][c] = 0.f;

        auto issueH = [&](int kt) {
            float* dst = sm + HA_OFF + (kt % 3) * HA_F;
#pragma unroll
            for (int s = 0; s < 4; s++) {
                int id = tid + s * 256, r = id >> 4, f4 = id & 15;
                cp16(dst + r * SHA + f4 * 4, h + (size_t)r * HDIM + kt * 64 + f4 * 4);
            }
            CP_COMMIT();
        };
        issueH(0);
        issueH(1);

        for (int kt = 0; kt < 16; kt++) {
            if (kt < 15) CP_WAIT(1); else CP_WAIT(0);
            __syncthreads();
            if (kt + 2 < 16) issueH(kt + 2);
            const float* Ab = sm + HA_OFF + (kt % 3) * HA_F;
            const float* Bb = Whs + kt * 64 * SWH;
#pragma unroll
            for (int ks = 0; ks < 64; ks += 8) {
                int r = wm * 16 + (lane >> 2);
                int cc = ks + (lane & 3);
                uint32_t a0 = __float_as_uint(Ab[r * SHA + cc]);
                uint32_t a1 = __float_as_uint(Ab[(r + 8) * SHA + cc]);
                uint32_t a2 = __float_as_uint(Ab[r * SHA + cc + 4]);
                uint32_t a3 = __float_as_uint(Ab[(r + 8) * SHA + cc + 4]);
#pragma unroll
                for (int ni = 0; ni < 2; ni++) {
                    int n = wn * 16 + ni * 8 + (lane >> 2);
                    uint32_t b0 = __float_as_uint(Bb[cc * SWH + n]);
                    uint32_t b1 = __float_as_uint(Bb[(cc + 4) * SWH + n]);
                    mma8(acc[ni], a0, a1, a2, a3, b0, b1);
                }
            }
        }
        __syncthreads();
#pragma unroll
        for (int ni = 0; ni < 2; ni++) {
            int r = wm * 16 + (lane >> 2);
            int c = wn * 16 + ni * 8 + (lane & 3) * 2;
            gbuf[r * 32 + c]           = acc[ni][0];
            gbuf[r * 32 + c + 1]       = acc[ni][1];
            gbuf[(r + 8) * 32 + c]     = acc[ni][2];
            gbuf[(r + 8) * 32 + c + 1] = acc[ni][3];
        }
        __syncthreads();

        const float* xgp = g_xg + ((size_t)t * NCTA + cta) * (BATCH * 32);
#pragma unroll
        for (int e = 0; e < 2; e++) {
            int idx = tid + e * 256;
            int b = idx >> 3, j = idx & 7;
            float4 gv = *(float4*)(gbuf + idx * 4);
            float4 xv = *(const float4*)(xgp + idx * 4);
            float fg = sigm(gv.x + xv.x);
            float ig = sigm(gv.y + xv.y);
            float gg = tanhf(gv.z + xv.z);
            float og = sigm(gv.w + xv.w);
            float c = fg * creg[e] + ig * gg;
            creg[e] = c;
            float hv = tanhf(c) * og;
            int go = b * HDIM + cta * 8 + j;
            if (t == TLEN - 1) {
                out[go] = hv;
                if (write_c) out[BATCH * HDIM + go] = c;
            }
            hn[go] = rna_f(hv);
        }
        gridbar();
    }
}

// ---- launch ----
extern "C" void kernel_launch(void* const* d_in, const int* in_sizes, int n_in,
                              void* d_out, int out_size) {
    const float* x = (const float*)d_in[0];
    const float *Wii, *Whi, *Wif, *Whf, *Wig, *Whg, *Wio, *Who;
    const float *bii, *bhi, *bif, *bhf, *big, *bhg, *bio, *bho;

    if (n_in >= 17 && in_sizes[2] == IDIM * HDIM) {
        // dict / metadata order: x, then 8 weights, then 8 biases
        Wii = (const float*)d_in[1];  Whi = (const float*)d_in[2];
        Wif = (const float*)d_in[3];  Whf = (const float*)d_in[4];
        Wig = (const float*)d_in[5];  Whg = (const float*)d_in[6];
        Wio = (const float*)d_in[7];  Who = (const float*)d_in[8];
        bii = (const float*)d_in[9];  bhi = (const float*)d_in[10];
        bif = (const float*)d_in[11]; bhf = (const float*)d_in[12];
        big = (const float*)d_in[13]; bhg = (const float*)d_in[14];
        bio = (const float*)d_in[15]; bho = (const float*)d_in[16];
    } else {
        // reference-signature order: x, W_ii, b_ii, W_hi, b_hi, ...
        Wii = (const float*)d_in[1];  bii = (const float*)d_in[2];
        Whi = (const float*)d_in[3];  bhi = (const float*)d_in[4];
        Wif = (const float*)d_in[5];  bif = (const float*)d_in[6];
        Whf = (const float*)d_in[7];  bhf = (const float*)d_in[8];
        Wig = (const float*)d_in[9];  big = (const float*)d_in[10];
        Whg = (const float*)d_in[11]; bhg = (const float*)d_in[12];
        Wio = (const float*)d_in[13]; bio = (const float*)d_in[14];
        Who = (const float*)d_in[15]; bho = (const float*)d_in[16];
    }
    float* out = (float*)d_out;

    cudaFuncSetAttribute(recur_kernel, cudaFuncAttributeMaxDynamicSharedMemorySize, REC_SMEM);

    prep_kernel<<<(IDIM * HDIM + 255) / 256, 256>>>(Wii, Whi, Wif, Whf, Wig, Whg, Wio, Who,
                                                    bii, bhi, bif, bhf, big, bhg, bio, bho);
    gemm1_kernel<<<256 * 32, 256>>>(x);
    int write_c = (out_size >= 2 * BATCH * HDIM) ? 1 : 0;
    recur_kernel<<<NCTA, 256, REC_SMEM>>>(out, write_c);
}